// round 1
// baseline (speedup 1.0000x reference)
#include <cuda_runtime.h>
#include <math.h>

// ---------------- problem constants ----------------
#define B_  4
#define S_  1024
#define D_  1024
#define E_  4
#define H_  2816           // HID
#define BS_ (B_*S_)        // 4096 tokens
#define CAP BS_            // worst-case tokens per expert
#define ADA6 (6*D_)        // 6144
#define BSD ((long)BS_*D_) // 4194304

// ---------------- device scratch (static, allocation-free) ----------------
__device__ float g_silu[B_*D_];
__device__ float g_ada [B_*ADA6];
__device__ float g_h   [BS_*D_];
__device__ float g_q   [BS_*D_];
__device__ float g_k   [BS_*D_];
__device__ float g_v   [BS_*D_];
__device__ float g_sc  [(long)B_*D_*D_];
__device__ float g_ao  [BS_*D_];
__device__ float g_x1  [BS_*D_];
__device__ float g_h2  [BS_*D_];
__device__ float g_lg  [BS_*E_];
__device__ float g_pr  [BS_*E_];
__device__ int   g_cnt [E_];
__device__ int   g_list[E_*CAP];
__device__ int   g_te  [BS_*2];
__device__ int   g_tp  [BS_*2];
__device__ float g_tw  [BS_*2];
__device__ float g_buf1[(long)E_*CAP*H_];   // h1 then sin(h1)*h3
__device__ float g_ebuf[(long)E_*CAP*D_];   // per-slot expert outputs

// ---------------- generic 128x128x8 fp32 GEMM ----------------
// MODE 0: C[M,N] = A[M,K] * B[K,N]           (A row-major lda=K, B row-major ldb=N)
// MODE 1: C[M,N] = A^T * B, A stored [K,M]   (lda=M), B [K,N]
// MODE 2: C[M,N] = A * B^T, B stored [N,K]   (ldb=K)
// EPI  0: store acc
// EPI  1: C = resid + gate[b,:]*acc   (b = row/S, gate row stride gateStride)
// EPI  2: C = sin(C_old) * acc        (C_old read from C itself)
template<int MODE, int EPI, bool GATHER>
__global__ void __launch_bounds__(256, 2) gemm_kernel(
    const float* __restrict__ A, const float* __restrict__ Bm, float* __restrict__ C,
    int M, int N, int K,
    long aStride, long bStride, long cStride,
    const int* __restrict__ gatherIdx, int gatherCap,
    const int* __restrict__ counts,
    const float* __restrict__ resid, const float* __restrict__ gate,
    int gateStride, int S)
{
    __shared__ float As[8][128];
    __shared__ float Bs[8][128];

    const int z  = blockIdx.z;
    const int m0 = blockIdx.x * 128;
    const int n0 = blockIdx.y * 128;
    const int Meff = counts ? counts[z] : M;
    if (m0 >= Meff) return;

    A += (long)z * aStride;
    Bm += (long)z * bStride;
    C += (long)z * cStride;

    const int tid = threadIdx.x;
    const int ar  = tid >> 1;          // 0..127
    const int ak  = (tid & 1) << 2;    // 0 or 4
    const int bkr = tid >> 5;          // 0..7
    const int bc  = (tid & 31) << 2;   // 0..124

    // A source
    const float* aSrc;
    bool aValid = true;
    if (MODE == 1) {
        aSrc = A + (long)bkr * M + m0 + bc;
    } else {
        int row = m0 + ar;
        aValid = (row < Meff);
        long arow = 0;
        if (aValid) arow = GATHER ? (long)gatherIdx[(long)z * gatherCap + row] : (long)row;
        aSrc = A + arow * (long)K + ak;
    }
    // B source
    const float* bSrc;
    if (MODE == 2) bSrc = Bm + (long)(n0 + ar) * K + ak;
    else           bSrc = Bm + (long)bkr * N + n0 + bc;

    float acc[8][8];
#pragma unroll
    for (int i = 0; i < 8; i++)
#pragma unroll
        for (int j = 0; j < 8; j++) acc[i][j] = 0.f;

    const int ty8 = (tid >> 4) << 3;
    const int tx8 = (tid & 15) << 3;

    for (int k0 = 0; k0 < K; k0 += 8) {
        if (MODE == 1) {
            float4 va = *(const float4*)(aSrc + (long)k0 * M);
            *(float4*)&As[bkr][bc] = va;
        } else {
            float4 va = make_float4(0.f, 0.f, 0.f, 0.f);
            if (aValid) va = *(const float4*)(aSrc + k0);
            As[ak + 0][ar] = va.x; As[ak + 1][ar] = va.y;
            As[ak + 2][ar] = va.z; As[ak + 3][ar] = va.w;
        }
        if (MODE == 2) {
            float4 vb = *(const float4*)(bSrc + k0);
            Bs[ak + 0][ar] = vb.x; Bs[ak + 1][ar] = vb.y;
            Bs[ak + 2][ar] = vb.z; Bs[ak + 3][ar] = vb.w;
        } else {
            float4 vb = *(const float4*)(bSrc + (long)k0 * N);
            *(float4*)&Bs[bkr][bc] = vb;
        }
        __syncthreads();
#pragma unroll
        for (int kk = 0; kk < 8; kk++) {
            float a[8], b[8];
            *(float4*)&a[0] = *(const float4*)&As[kk][ty8];
            *(float4*)&a[4] = *(const float4*)&As[kk][ty8 + 4];
            *(float4*)&b[0] = *(const float4*)&Bs[kk][tx8];
            *(float4*)&b[4] = *(const float4*)&Bs[kk][tx8 + 4];
#pragma unroll
            for (int i = 0; i < 8; i++)
#pragma unroll
                for (int j = 0; j < 8; j++)
                    acc[i][j] = fmaf(a[i], b[j], acc[i][j]);
        }
        __syncthreads();
    }

    // epilogue
#pragma unroll
    for (int i = 0; i < 8; i++) {
        int r = m0 + ty8 + i;
        if (r >= Meff) break;
        long off = (long)r * N + n0 + tx8;
#pragma unroll
        for (int jj = 0; jj < 8; jj += 4) {
            float4 o;
            o.x = acc[i][jj + 0]; o.y = acc[i][jj + 1];
            o.z = acc[i][jj + 2]; o.w = acc[i][jj + 3];
            if (EPI == 1) {
                int bb = r / S;
                float4 rv = *(const float4*)&resid[off + jj];
                float4 gv = *(const float4*)&gate[(long)bb * gateStride + n0 + tx8 + jj];
                o.x = rv.x + gv.x * o.x; o.y = rv.y + gv.y * o.y;
                o.z = rv.z + gv.z * o.z; o.w = rv.w + gv.w * o.w;
            } else if (EPI == 2) {
                float4 old = *(const float4*)&C[off + jj];
                o.x = sinf(old.x) * o.x; o.y = sinf(old.y) * o.y;
                o.z = sinf(old.z) * o.z; o.w = sinf(old.w) * o.w;
            }
            *(float4*)&C[off + jj] = o;
        }
    }
}

// ---------------- small kernels ----------------
__global__ void silu_kernel(const float* __restrict__ in, float* __restrict__ o) {
    int i = blockIdx.x * 256 + threadIdx.x;
    if (i < B_ * D_) { float v = in[i]; o[i] = v / (1.f + expf(-v)); }
}

// ada = silu(adaln) @ ada_w + ada_b    [B,6D], 128 threads/block, 48 blocks
__global__ void __launch_bounds__(128) ada_kernel(const float* __restrict__ sl,
                                                  const float* __restrict__ W,
                                                  const float* __restrict__ bias,
                                                  float* __restrict__ ada) {
    __shared__ float s[B_ * D_];
    int col = blockIdx.x * 128 + threadIdx.x;
    for (int i = threadIdx.x; i < B_ * D_; i += 128) s[i] = sl[i];
    __syncthreads();
    float a0 = 0.f, a1 = 0.f, a2 = 0.f, a3 = 0.f;
    for (int k = 0; k < D_; k++) {
        float w = W[(long)k * ADA6 + col];
        a0 = fmaf(s[k], w, a0);
        a1 = fmaf(s[D_ + k], w, a1);
        a2 = fmaf(s[2 * D_ + k], w, a2);
        a3 = fmaf(s[3 * D_ + k], w, a3);
    }
    float bv = bias[col];
    ada[col] = a0 + bv;
    ada[ADA6 + col] = a1 + bv;
    ada[2L * ADA6 + col] = a2 + bv;
    ada[3L * ADA6 + col] = a3 + bv;
}

// LayerNorm over last dim (=1024), optional adaLN modulation
__global__ void __launch_bounds__(256) ln_kernel(const float* __restrict__ in, float* __restrict__ out,
    const float* __restrict__ w, const float* __restrict__ b,
    const float* __restrict__ scale, const float* __restrict__ shift,
    int adaStride, int S, float eps)
{
    long row = blockIdx.x;
    const float* xr = in + row * D_;
    int t = threadIdx.x;
    float4 v = *(const float4*)&xr[t * 4];
    float s1 = v.x + v.y + v.z + v.w;
    float s2 = v.x * v.x + v.y * v.y + v.z * v.z + v.w * v.w;
    __shared__ float sm[16];
#pragma unroll
    for (int o = 16; o; o >>= 1) {
        s1 += __shfl_down_sync(0xffffffffu, s1, o);
        s2 += __shfl_down_sync(0xffffffffu, s2, o);
    }
    if ((t & 31) == 0) { sm[t >> 5] = s1; sm[8 + (t >> 5)] = s2; }
    __syncthreads();
    if (t == 0) {
        float a = 0.f, c = 0.f;
        for (int i = 0; i < 8; i++) { a += sm[i]; c += sm[8 + i]; }
        sm[0] = a; sm[8] = c;
    }
    __syncthreads();
    float mean = sm[0] * (1.f / D_);
    float var = sm[8] * (1.f / D_) - mean * mean;
    float rs = rsqrtf(var + eps);
    int c0 = t * 4;
    float4 wv = *(const float4*)&w[c0];
    float4 bv = *(const float4*)&b[c0];
    float4 o;
    o.x = (v.x - mean) * rs * wv.x + bv.x;
    o.y = (v.y - mean) * rs * wv.y + bv.y;
    o.z = (v.z - mean) * rs * wv.z + bv.z;
    o.w = (v.w - mean) * rs * wv.w + bv.w;
    if (scale) {
        int bb = (int)(row / S);
        float4 sv = *(const float4*)&scale[(long)bb * adaStride + c0];
        float4 hv = *(const float4*)&shift[(long)bb * adaStride + c0];
        o.x = o.x * (1.f + sv.x) + hv.x;
        o.y = o.y * (1.f + sv.y) + hv.y;
        o.z = o.z * (1.f + sv.z) + hv.z;
        o.w = o.w * (1.f + sv.w) + hv.w;
    }
    *(float4*)&out[row * D_ + c0] = o;
}

// row softmax, width 1024, in place
__global__ void __launch_bounds__(256) softmax_kernel(float* __restrict__ p) {
    long row = blockIdx.x;
    float* r = p + row * D_;
    int t = threadIdx.x;
    float4 v = *(const float4*)&r[t * 4];
    float m = fmaxf(fmaxf(v.x, v.y), fmaxf(v.z, v.w));
    __shared__ float sm[8];
#pragma unroll
    for (int o = 16; o; o >>= 1) m = fmaxf(m, __shfl_down_sync(0xffffffffu, m, o));
    if ((t & 31) == 0) sm[t >> 5] = m;
    __syncthreads();
    if (t == 0) { float a = sm[0]; for (int i = 1; i < 8; i++) a = fmaxf(a, sm[i]); sm[0] = a; }
    __syncthreads();
    m = sm[0];
    float e0 = expf(v.x - m), e1 = expf(v.y - m), e2 = expf(v.z - m), e3 = expf(v.w - m);
    float s = e0 + e1 + e2 + e3;
    __syncthreads();
#pragma unroll
    for (int o = 16; o; o >>= 1) s += __shfl_down_sync(0xffffffffu, s, o);
    if ((t & 31) == 0) sm[t >> 5] = s;
    __syncthreads();
    if (t == 0) { float a = 0.f; for (int i = 0; i < 8; i++) a += sm[i]; sm[0] = a; }
    __syncthreads();
    float inv = 1.f / sm[0];
    *(float4*)&r[t * 4] = make_float4(e0 * inv, e1 * inv, e2 * inv, e3 * inv);
}

// router logits: one block per token, 4 outputs
__global__ void __launch_bounds__(256) router_kernel(const float* __restrict__ h,
    const float* __restrict__ rw, const float* __restrict__ rb, float* __restrict__ lg)
{
    int tok = blockIdx.x;
    const float* hr = h + (long)tok * D_;
    int t = threadIdx.x;
    float4 hv = *(const float4*)&hr[t * 4];
    float hvv[4] = { hv.x, hv.y, hv.z, hv.w };
    float a0 = 0.f, a1 = 0.f, a2 = 0.f, a3 = 0.f;
#pragma unroll
    for (int j = 0; j < 4; j++) {
        int k = t * 4 + j;
        float4 w = *(const float4*)&rw[(long)k * 4];
        float xv = hvv[j];
        a0 = fmaf(xv, w.x, a0); a1 = fmaf(xv, w.y, a1);
        a2 = fmaf(xv, w.z, a2); a3 = fmaf(xv, w.w, a3);
    }
#pragma unroll
    for (int o = 16; o; o >>= 1) {
        a0 += __shfl_down_sync(0xffffffffu, a0, o);
        a1 += __shfl_down_sync(0xffffffffu, a1, o);
        a2 += __shfl_down_sync(0xffffffffu, a2, o);
        a3 += __shfl_down_sync(0xffffffffu, a3, o);
    }
    __shared__ float sm[8][4];
    if ((t & 31) == 0) { int w5 = t >> 5; sm[w5][0] = a0; sm[w5][1] = a1; sm[w5][2] = a2; sm[w5][3] = a3; }
    __syncthreads();
    if (t < 4) {
        float s = 0.f;
        for (int i = 0; i < 8; i++) s += sm[i][t];
        lg[(long)tok * 4 + t] = s + rb[t];
    }
}

// L2-normalize logits along SEQUENCE dim (faithful quirk). block per (b,e)
__global__ void __launch_bounds__(256) seqnorm_kernel(float* __restrict__ lg) {
    int b = blockIdx.x >> 2, e = blockIdx.x & 3;
    int t = threadIdx.x;
    float s = 0.f;
    for (int i = t; i < S_; i += 256) {
        float v = lg[((long)(b * S_ + i)) * 4 + e];
        s += v * v;
    }
    __shared__ float sm[8];
#pragma unroll
    for (int o = 16; o; o >>= 1) s += __shfl_down_sync(0xffffffffu, s, o);
    if ((t & 31) == 0) sm[t >> 5] = s;
    __syncthreads();
    if (t == 0) {
        float a = 0.f;
        for (int i = 0; i < 8; i++) a += sm[i];
        sm[0] = 1.f / fmaxf(sqrtf(a), 1e-12f);
    }
    __syncthreads();
    float sc = sm[0];
    for (int i = t; i < S_; i += 256) lg[((long)(b * S_ + i)) * 4 + e] *= sc;
}

__global__ void zero_kernel(int* cnt) { if (threadIdx.x < E_) cnt[threadIdx.x] = 0; }

// softmax over E, top-2, build expert dispatch lists + per-token slot meta
__global__ void topk_kernel(const float* __restrict__ lg, float* __restrict__ pr,
    int* __restrict__ cnt, int* __restrict__ list,
    int* __restrict__ te, int* __restrict__ tp, float* __restrict__ tw)
{
    int tok = blockIdx.x * 256 + threadIdx.x;
    if (tok >= BS_) return;
    float l[4];
#pragma unroll
    for (int e = 0; e < 4; e++) l[e] = lg[(long)tok * 4 + e];
    float m = fmaxf(fmaxf(l[0], l[1]), fmaxf(l[2], l[3]));
    float p[4]; float s = 0.f;
#pragma unroll
    for (int e = 0; e < 4; e++) { p[e] = expf(l[e] - m); s += p[e]; }
    float inv = 1.f / s;
#pragma unroll
    for (int e = 0; e < 4; e++) { p[e] *= inv; pr[(long)tok * 4 + e] = p[e]; }
    int a0 = 0;
#pragma unroll
    for (int e = 1; e < 4; e++) if (p[e] > p[a0]) a0 = e;
    int a1 = -1; float pb = -1.f;
#pragma unroll
    for (int e = 0; e < 4; e++) if (e != a0 && p[e] > pb) { pb = p[e]; a1 = e; }
    int s0 = atomicAdd(&cnt[a0], 1); list[a0 * CAP + s0] = tok;
    int s1 = atomicAdd(&cnt[a1], 1); list[a1 * CAP + s1] = tok;
    te[2 * tok] = a0;     tp[2 * tok] = s0;     tw[2 * tok] = p[a0];
    te[2 * tok + 1] = a1; tp[2 * tok + 1] = s1; tw[2 * tok + 1] = p[a1];
}

// out[tok,d] = w0*ebuf[e0][p0][d] + w1*ebuf[e1][p1][d]   (deterministic per-token gather)
__global__ void combine_kernel(const float* __restrict__ ebuf,
    const int* __restrict__ te, const int* __restrict__ tp,
    const float* __restrict__ tw, float* __restrict__ out)
{
    long gid = (long)blockIdx.x * 256 + threadIdx.x;
    int tok = (int)(gid >> 10);
    int d = (int)(gid & 1023);
    int e0 = te[2 * tok], e1 = te[2 * tok + 1];
    long r0 = ((long)e0 * CAP + tp[2 * tok]) * D_ + d;
    long r1 = ((long)e1 * CAP + tp[2 * tok + 1]) * D_ + d;
    out[gid] = tw[2 * tok] * ebuf[r0] + tw[2 * tok + 1] * ebuf[r1];
}

// aux = sum_{s,e} (1/E - mean_b probs)^2 ; write to out[BSD..out_size)
__global__ void __launch_bounds__(256) aux_kernel(const float* __restrict__ pr,
                                                  float* __restrict__ out, long out_size)
{
    int t = threadIdx.x;
    float acc = 0.f;
    for (int i = t; i < S_ * E_; i += 256) {
        int s = i >> 2, e = i & 3;
        float av = 0.f;
#pragma unroll
        for (int b = 0; b < B_; b++) av += pr[((long)(b * S_ + s)) * 4 + e];
        av *= 0.25f;
        float d = 0.25f - av;
        acc += d * d;
    }
    __shared__ float sm[8];
#pragma unroll
    for (int o = 16; o; o >>= 1) acc += __shfl_down_sync(0xffffffffu, acc, o);
    if ((t & 31) == 0) sm[t >> 5] = acc;
    __syncthreads();
    if (t == 0) {
        float a = 0.f;
        for (int i = 0; i < 8; i++) a += sm[i];
        for (long i = BSD; i < out_size; i++) out[i] = a;
    }
}

// ---------------- host launcher ----------------
extern "C" void kernel_launch(void* const* d_in, const int* in_sizes, int n_in,
                              void* d_out, int out_size)
{
    (void)in_sizes; (void)n_in;
    const float* x     = (const float*)d_in[0];
    const float* adaln = (const float*)d_in[2];
    const float* wq    = (const float*)d_in[3];
    const float* wk    = (const float*)d_in[4];
    const float* wv    = (const float*)d_in[5];
    const float* wo    = (const float*)d_in[6];
    const float* qnw   = (const float*)d_in[7];
    const float* qnb   = (const float*)d_in[8];
    const float* knw   = (const float*)d_in[9];
    const float* knb   = (const float*)d_in[10];
    const float* anw   = (const float*)d_in[11];
    const float* anb   = (const float*)d_in[12];
    const float* w1    = (const float*)d_in[15];
    const float* w2    = (const float*)d_in[16];
    const float* w3    = (const float*)d_in[17];
    const float* rw    = (const float*)d_in[18];
    const float* rb    = (const float*)d_in[19];
    const float* adaw  = (const float*)d_in[20];
    const float* adab  = (const float*)d_in[21];
    const float* fnw   = (const float*)d_in[13];
    const float* fnb   = (const float*)d_in[14];
    float* out = (float*)d_out;

    float *silu_, *ada_, *h_, *q_, *k_, *v_, *sc_, *ao_, *x1_, *h2_, *lg_, *pr_, *buf1_, *ebuf_, *tw_;
    int *cnt_, *list_, *te_, *tp_;
    cudaGetSymbolAddress((void**)&silu_, g_silu);
    cudaGetSymbolAddress((void**)&ada_,  g_ada);
    cudaGetSymbolAddress((void**)&h_,    g_h);
    cudaGetSymbolAddress((void**)&q_,    g_q);
    cudaGetSymbolAddress((void**)&k_,    g_k);
    cudaGetSymbolAddress((void**)&v_,    g_v);
    cudaGetSymbolAddress((void**)&sc_,   g_sc);
    cudaGetSymbolAddress((void**)&ao_,   g_ao);
    cudaGetSymbolAddress((void**)&x1_,   g_x1);
    cudaGetSymbolAddress((void**)&h2_,   g_h2);
    cudaGetSymbolAddress((void**)&lg_,   g_lg);
    cudaGetSymbolAddress((void**)&pr_,   g_pr);
    cudaGetSymbolAddress((void**)&buf1_, g_buf1);
    cudaGetSymbolAddress((void**)&ebuf_, g_ebuf);
    cudaGetSymbolAddress((void**)&tw_,   g_tw);
    cudaGetSymbolAddress((void**)&cnt_,  g_cnt);
    cudaGetSymbolAddress((void**)&list_, g_list);
    cudaGetSymbolAddress((void**)&te_,   g_te);
    cudaGetSymbolAddress((void**)&tp_,   g_tp);

    const float eps = 1e-5f;
    const long SD = (long)S_ * D_;
    const long DDl = (long)D_ * D_;

    // 1. adaLN modulation vectors
    silu_kernel<<<(B_*D_ + 255) / 256, 256>>>(adaln, silu_);
    ada_kernel<<<ADA6 / 128, 128>>>(silu_, adaw, adab, ada_);

    // 2. h = modulate(LN(x), msa)
    ln_kernel<<<BS_, 256>>>(x, h_, anw, anb, ada_ + D_, ada_, ADA6, S_, eps);

    // 3. q,k,v GEMMs
    gemm_kernel<0,0,false><<<dim3(32, 8, 1), 256>>>(h_, wq, q_, BS_, D_, D_, 0,0,0,
        nullptr,0,nullptr, nullptr,nullptr,0,0);
    gemm_kernel<0,0,false><<<dim3(32, 8, 1), 256>>>(h_, wk, k_, BS_, D_, D_, 0,0,0,
        nullptr,0,nullptr, nullptr,nullptr,0,0);
    gemm_kernel<0,0,false><<<dim3(32, 8, 1), 256>>>(h_, wv, v_, BS_, D_, D_, 0,0,0,
        nullptr,0,nullptr, nullptr,nullptr,0,0);

    // 4. q_norm / k_norm (in place)
    ln_kernel<<<BS_, 256>>>(q_, q_, qnw, qnb, nullptr, nullptr, 0, S_, eps);
    ln_kernel<<<BS_, 256>>>(k_, k_, knw, knb, nullptr, nullptr, 0, S_, eps);

    // 5. scores[b] = q[b]^T @ k[b]   (feature-dim attention, [B,D,D])
    gemm_kernel<1,0,false><<<dim3(8, 8, B_), 256>>>(q_, k_, sc_, D_, D_, S_,
        SD, SD, DDl, nullptr,0,nullptr, nullptr,nullptr,0,0);

    // 6. softmax over last dim
    softmax_kernel<<<B_ * D_, 256>>>(sc_);

    // 7. attn_out[b] = v[b] @ attn[b]^T
    gemm_kernel<2,0,false><<<dim3(8, 8, B_), 256>>>(v_, sc_, ao_, S_, D_, D_,
        SD, DDl, SD, nullptr,0,nullptr, nullptr,nullptr,0,0);

    // 8. x1 = x + gate_msa * (attn_out @ wo)
    gemm_kernel<0,1,false><<<dim3(32, 8, 1), 256>>>(ao_, wo, x1_, BS_, D_, D_, 0,0,0,
        nullptr,0,nullptr, x, ada_ + 2L*D_, ADA6, S_);

    // 9. h2 = modulate(LN(x1), mlp)
    ln_kernel<<<BS_, 256>>>(x1_, h2_, fnw, fnb, ada_ + 4L*D_, ada_ + 3L*D_, ADA6, S_, eps);

    // 10. router + seq-dim L2 norm + softmax/top2 dispatch
    router_kernel<<<BS_, 256>>>(h2_, rw, rb, lg_);
    seqnorm_kernel<<<B_ * E_, 256>>>(lg_);
    zero_kernel<<<1, 32>>>(cnt_);
    topk_kernel<<<BS_ / 256, 256>>>(lg_, pr_, cnt_, list_, te_, tp_, tw_);

    // 11. expert up-projections (gathered rows), gated = sin(h1) * h3
    gemm_kernel<0,0,true><<<dim3(CAP / 128, H_ / 128, E_), 256>>>(h2_, w1, buf1_,
        CAP, H_, D_, 0, (long)D_ * H_, (long)CAP * H_, list_, CAP, cnt_,
        nullptr, nullptr, 0, 0);
    gemm_kernel<0,2,true><<<dim3(CAP / 128, H_ / 128, E_), 256>>>(h2_, w3, buf1_,
        CAP, H_, D_, 0, (long)D_ * H_, (long)CAP * H_, list_, CAP, cnt_,
        nullptr, nullptr, 0, 0);

    // 12. expert down-projection
    gemm_kernel<0,0,false><<<dim3(CAP / 128, D_ / 128, E_), 256>>>(buf1_, w2, ebuf_,
        CAP, D_, H_, (long)CAP * H_, (long)H_ * D_, (long)CAP * D_,
        nullptr, 0, cnt_, nullptr, nullptr, 0, 0);

    // 13. per-token combine -> d_out, then aux scalar
    combine_kernel<<<(int)(BSD / 256), 256>>>(ebuf_, te_, tp_, tw_, out);
    aux_kernel<<<1, 256>>>(pr_, out, (long)out_size);
}